// round 1
// baseline (speedup 1.0000x reference)
#include <cuda_runtime.h>
#include <math.h>

#define BATCH 8
#define NV 2048
#define NP 4096
#define DIM 64
#define TOPK 8

// ---------------- scratch (device globals; no allocation) ----------------
__device__ float g_pf_unit[BATCH * NP * DIM];   // 8 MB  : unit-normalized pts_feature
__device__ float g_vf_unit[BATCH * NV * DIM];   // 4 MB  : unit-normalized vtx_feature
__device__ float g_vm[BATCH * NV];              // normalized sigmoid(vismask)
__device__ int   g_vis[BATCH * NV];             // vm >= 0.5
__device__ float g_visbias[BATCH * NV];         // 0 if visible else -1e30 (stage2 mask)
__device__ float g_flow[BATCH * NV * 3];        // flow_init

// ---------------- kernel A: vm = minmax-normalized sigmoid ----------------
__global__ void vm_kernel(const float* __restrict__ logits) {
    const int b = blockIdx.x;
    __shared__ float sv[NV];
    __shared__ float smin[256];
    __shared__ float smax[256];
    float lmin = 1e30f, lmax = -1e30f;
    for (int i = threadIdx.x; i < NV; i += 256) {
        float s = 1.0f / (1.0f + expf(-logits[b * NV + i]));
        sv[i] = s;
        lmin = fminf(lmin, s);
        lmax = fmaxf(lmax, s);
    }
    smin[threadIdx.x] = lmin;
    smax[threadIdx.x] = lmax;
    __syncthreads();
    for (int off = 128; off > 0; off >>= 1) {
        if (threadIdx.x < off) {
            smin[threadIdx.x] = fminf(smin[threadIdx.x], smin[threadIdx.x + off]);
            smax[threadIdx.x] = fmaxf(smax[threadIdx.x], smax[threadIdx.x + off]);
        }
        __syncthreads();
    }
    const float mn = smin[0];
    const float inv = 1.0f / (smax[0] - mn);
    for (int i = threadIdx.x; i < NV; i += 256) {
        float v = (sv[i] - mn) * inv;
        g_vm[b * NV + i] = v;
        int vis = (v >= 0.5f) ? 1 : 0;
        g_vis[b * NV + i] = vis;
        g_visbias[b * NV + i] = vis ? 0.0f : -1e30f;
    }
}

// ---------------- kernel B: unit-normalize key features ----------------
// one warp per row; lane handles 2 consecutive floats (float2, coalesced)
__global__ void norm_kernel(const float* __restrict__ vf, const float* __restrict__ pf) {
    const int gw = (blockIdx.x * blockDim.x + threadIdx.x) >> 5;
    const int lane = threadIdx.x & 31;
    const int totalRows = BATCH * NV + BATCH * NP;
    if (gw >= totalRows) return;
    const float* src;
    float* dst;
    if (gw < BATCH * NV) {
        src = vf + (size_t)gw * DIM;
        dst = g_vf_unit + (size_t)gw * DIM;
    } else {
        const int r = gw - BATCH * NV;
        src = pf + (size_t)r * DIM;
        dst = g_pf_unit + (size_t)r * DIM;
    }
    float2 v = ((const float2*)src)[lane];
    float ss = v.x * v.x + v.y * v.y;
#pragma unroll
    for (int o = 16; o > 0; o >>= 1) ss += __shfl_xor_sync(0xffffffffu, ss, o);
    const float n = sqrtf(ss);
    const float inv = 1.0f / fmaxf(n, 1e-12f);
    float2 o2;
    o2.x = v.x * inv;
    o2.y = v.y * inv;
    ((float2*)dst)[lane] = o2;
}

// sorted-insert helper semantics (inlined below): v[0..7] ascending, v[0] = current min.

// ---------------- stage 1: KNN vtx->pts + flow_init ----------------
// block = 256 threads = 8 warps. lane <-> query (32 queries/block).
// warp w scans key chunk [w*512, w*512+512) of the batch's 4096 pts.
__global__ __launch_bounds__(256, 2) void stage1_kernel(
    const float* __restrict__ vtx, const float* __restrict__ pts,
    const float* __restrict__ vf_raw, const float* __restrict__ pf_raw) {
    const int tid = threadIdx.x;
    const int w = tid >> 5;
    const int lane = tid & 31;
    const int qg = blockIdx.x * 32 + lane;  // global query vertex
    const int b = qg >> 11;                 // / NV

    // query features (raw) in registers: ranking is invariant to query norm
    float4 q[16];
    {
        const float4* qr = (const float4*)(vf_raw + (size_t)qg * DIM);
#pragma unroll
        for (int i = 0; i < 16; i++) q[i] = qr[i];
    }

    __shared__ float4 tile[8][16][16];  // [warp][key][dim4]  32 KB
    __shared__ float mval[32][64];      // merge buffer        8 KB
    __shared__ int midx[32][64];        //                     8 KB

    float v[8];
    int id[8];
#pragma unroll
    for (int j = 0; j < 8; j++) {
        v[j] = -1e30f;
        id[j] = -1;
    }

    const float* pfU = g_pf_unit + (size_t)b * NP * DIM;
    const int chunkBase = w * 512;

    for (int t = 0; t < 32; t++) {
        const int keyBase = chunkBase + t * 16;
        // cooperative (per-warp) tile load: 16 keys x 64 floats = 256 float4
        const float4* src = (const float4*)(pfU + (size_t)keyBase * DIM);
        float4* dstT = &tile[w][0][0];
#pragma unroll
        for (int i = 0; i < 8; i++) dstT[lane + i * 32] = src[lane + i * 32];
        __syncwarp();
#pragma unroll 2
        for (int k = 0; k < 16; k++) {
            float a0 = 0.f, a1 = 0.f, a2 = 0.f, a3 = 0.f;
#pragma unroll
            for (int d = 0; d < 16; d++) {
                float4 kv = tile[w][k][d];  // broadcast LDS.128
                a0 += q[d].x * kv.x;
                a1 += q[d].y * kv.y;
                a2 += q[d].z * kv.z;
                a3 += q[d].w * kv.w;
            }
            float s = (a0 + a1) + (a2 + a3);
            if (s > v[0]) {
                v[0] = s;
                id[0] = keyBase + k;
#pragma unroll
                for (int j = 0; j < 7; j++) {
                    if (v[j] > v[j + 1]) {
                        float tv = v[j]; v[j] = v[j + 1]; v[j + 1] = tv;
                        int ti = id[j]; id[j] = id[j + 1]; id[j + 1] = ti;
                    }
                }
            }
        }
        __syncwarp();
    }

    // publish per-chunk top8
#pragma unroll
    for (int j = 0; j < 8; j++) {
        mval[lane][w * 8 + j] = v[j];
        midx[lane][w * 8 + j] = id[j];
    }
    __syncthreads();

    if (w == 0) {
        // final merge over 64 candidates for query qg
        float bv[8];
        int bi[8];
#pragma unroll
        for (int j = 0; j < 8; j++) {
            bv[j] = -1e30f;
            bi[j] = -1;
        }
        for (int c = 0; c < 64; c++) {
            float s = mval[lane][c];
            if (s > bv[0]) {
                bv[0] = s;
                bi[0] = midx[lane][c];
#pragma unroll
                for (int j = 0; j < 7; j++) {
                    if (bv[j] > bv[j + 1]) {
                        float tv = bv[j]; bv[j] = bv[j + 1]; bv[j + 1] = tv;
                        int ti = bi[j]; bi[j] = bi[j + 1]; bi[j + 1] = ti;
                    }
                }
            }
        }
        // epilogue: flow_init = sum(euclid * fsim) / sum(fsim); vm cancels.
        const float vx = vtx[qg * 3 + 0];
        const float vy = vtx[qg * 3 + 1];
        const float vz = vtx[qg * 3 + 2];
        float n0 = 0.f, n1 = 0.f, n2 = 0.f, den = 0.f;
#pragma unroll
        for (int j = 0; j < 8; j++) {
            const int gp = b * NP + bi[j];
            const float4* pr = (const float4*)(pf_raw + (size_t)gp * DIM);
            float f0 = 0.f, f1 = 0.f, f2 = 0.f, f3 = 0.f;
#pragma unroll
            for (int i = 0; i < 16; i++) {
                float4 pv = pr[i];
                f0 += q[i].x * pv.x;
                f1 += q[i].y * pv.y;
                f2 += q[i].z * pv.z;
                f3 += q[i].w * pv.w;
            }
            const float f = (f0 + f1) + (f2 + f3);
            n0 += (pts[gp * 3 + 0] - vx) * f;
            n1 += (pts[gp * 3 + 1] - vy) * f;
            n2 += (pts[gp * 3 + 2] - vz) * f;
            den += f;
        }
        const float invd = 1.0f / den;
        g_flow[qg * 3 + 0] = n0 * invd;
        g_flow[qg * 3 + 1] = n1 * invd;
        g_flow[qg * 3 + 2] = n2 * invd;
    }
}

// ---------------- stage 2: KNN vtx->visible vtx, invisible interp, output ----------------
__global__ __launch_bounds__(256, 2) void stage2_kernel(
    const float* __restrict__ vf_raw, float* __restrict__ out) {
    const int tid = threadIdx.x;
    const int w = tid >> 5;
    const int lane = tid & 31;
    const int qg = blockIdx.x * 32 + lane;
    const int b = qg >> 11;

    float4 q[16];
    {
        const float4* qr = (const float4*)(vf_raw + (size_t)qg * DIM);
#pragma unroll
        for (int i = 0; i < 16; i++) q[i] = qr[i];
    }

    __shared__ float4 tile[8][16][16];  // 32 KB
    __shared__ float mval[32][64];      //  8 KB
    __shared__ int midx[32][64];        //  8 KB

    float v[8];
    int id[8];
#pragma unroll
    for (int j = 0; j < 8; j++) {
        v[j] = -1e30f;
        id[j] = -1;
    }

    const float* vfU = g_vf_unit + (size_t)b * NV * DIM;
    const float* biasB = g_visbias + b * NV;
    const int chunkBase = w * 256;  // 2048 keys / 8 warps

    for (int t = 0; t < 16; t++) {
        const int keyBase = chunkBase + t * 16;
        const float4* src = (const float4*)(vfU + (size_t)keyBase * DIM);
        float4* dstT = &tile[w][0][0];
#pragma unroll
        for (int i = 0; i < 8; i++) dstT[lane + i * 32] = src[lane + i * 32];
        __syncwarp();
#pragma unroll 2
        for (int k = 0; k < 16; k++) {
            float a0 = 0.f, a1 = 0.f, a2 = 0.f, a3 = 0.f;
#pragma unroll
            for (int d = 0; d < 16; d++) {
                float4 kv = tile[w][k][d];
                a0 += q[d].x * kv.x;
                a1 += q[d].y * kv.y;
                a2 += q[d].z * kv.z;
                a3 += q[d].w * kv.w;
            }
            // invisible keys get -1e30 bias -> never selected
            float s = (a0 + a1) + (a2 + a3) + biasB[keyBase + k];
            if (s > v[0]) {
                v[0] = s;
                id[0] = keyBase + k;
#pragma unroll
                for (int j = 0; j < 7; j++) {
                    if (v[j] > v[j + 1]) {
                        float tv = v[j]; v[j] = v[j + 1]; v[j + 1] = tv;
                        int ti = id[j]; id[j] = id[j + 1]; id[j + 1] = ti;
                    }
                }
            }
        }
        __syncwarp();
    }

#pragma unroll
    for (int j = 0; j < 8; j++) {
        mval[lane][w * 8 + j] = v[j];
        midx[lane][w * 8 + j] = id[j];
    }
    __syncthreads();

    if (w == 0) {
        const float vmq = g_vm[qg];
        const int visq = g_vis[qg];
        float o0, o1, o2;
        if (visq) {
            o0 = g_flow[qg * 3 + 0];
            o1 = g_flow[qg * 3 + 1];
            o2 = g_flow[qg * 3 + 2];
        } else {
            float bv[8];
            int bi[8];
#pragma unroll
            for (int j = 0; j < 8; j++) {
                bv[j] = -1e30f;
                bi[j] = -1;
            }
            for (int c = 0; c < 64; c++) {
                float s = mval[lane][c];
                if (s > bv[0]) {
                    bv[0] = s;
                    bi[0] = midx[lane][c];
#pragma unroll
                    for (int j = 0; j < 7; j++) {
                        if (bv[j] > bv[j + 1]) {
                            float tv = bv[j]; bv[j] = bv[j + 1]; bv[j + 1] = tv;
                            int ti = bi[j]; bi[j] = bi[j + 1]; bi[j + 1] = ti;
                        }
                    }
                }
            }
            float n0 = 0.f, n1 = 0.f, n2 = 0.f, den = 0.f;
#pragma unroll
            for (int j = 0; j < 8; j++) {
                const int gv = b * NV + bi[j];
                const float4* kr = (const float4*)(vf_raw + (size_t)gv * DIM);
                float f0 = 0.f, f1 = 0.f, f2 = 0.f, f3 = 0.f;
#pragma unroll
                for (int i = 0; i < 16; i++) {
                    float4 kv = kr[i];
                    f0 += q[i].x * kv.x;
                    f1 += q[i].y * kv.y;
                    f2 += q[i].z * kv.z;
                    f3 += q[i].w * kv.w;
                }
                const float f = (f0 + f1) + (f2 + f3);
                n0 += g_flow[gv * 3 + 0] * f;
                n1 += g_flow[gv * 3 + 1] * f;
                n2 += g_flow[gv * 3 + 2] * f;
                den += f;
            }
            const float invd = 1.0f / den;
            o0 = n0 * invd;
            o1 = n1 * invd;
            o2 = n2 * invd;
        }
        out[qg * 4 + 0] = o0;
        out[qg * 4 + 1] = o1;
        out[qg * 4 + 2] = o2;
        out[qg * 4 + 3] = vmq;
    }
}

// ---------------- launch ----------------
extern "C" void kernel_launch(void* const* d_in, const int* in_sizes, int n_in,
                              void* d_out, int out_size) {
    const float* vtx = (const float*)d_in[0];
    const float* pts = (const float*)d_in[1];
    const float* vf = (const float*)d_in[2];
    const float* pf = (const float*)d_in[3];
    const float* vml = (const float*)d_in[4];
    float* out = (float*)d_out;

    vm_kernel<<<BATCH, 256>>>(vml);
    const int rows = BATCH * (NV + NP);          // 49152 rows, warp per row
    norm_kernel<<<(rows * 32) / 256, 256>>>(vf, pf);
    stage1_kernel<<<(BATCH * NV) / 32, 256>>>(vtx, pts, vf, pf);
    stage2_kernel<<<(BATCH * NV) / 32, 256>>>(vf, out);
}

// round 2
// speedup vs baseline: 1.2258x; 1.2258x over previous
#include <cuda_runtime.h>
#include <math.h>

#define BATCH 8
#define NV 2048
#define NP 4096
#define DIM 64

// ---------------- scratch (device globals; no allocation) ----------------
__device__ float g_pf_unit[BATCH * NP * DIM];   // unit-normalized pts_feature
__device__ float g_vf_unit[BATCH * NV * DIM];   // unit-normalized vtx_feature
__device__ float g_vm[BATCH * NV];              // normalized sigmoid(vismask)
__device__ float g_flow[BATCH * NV * 3];        // flow_init
__device__ int   g_invis_list[BATCH * NV];      // compacted invisible query ids (per batch)
__device__ int   g_vis_list[BATCH * NV];        // compacted visible key ids (per batch)
__device__ int   g_invis_cnt[BATCH];
__device__ int   g_vis_cnt[BATCH];

// ---------------- f32x2 helpers ----------------
__device__ __forceinline__ void fma2(unsigned long long& d, unsigned long long a,
                                     unsigned long long b) {
    asm("fma.rn.f32x2 %0, %1, %2, %0;" : "+l"(d) : "l"(a), "l"(b));
}
__device__ __forceinline__ unsigned long long add2(unsigned long long a, unsigned long long b) {
    unsigned long long d;
    asm("add.rn.f32x2 %0, %1, %2;" : "=l"(d) : "l"(a), "l"(b));
    return d;
}
__device__ __forceinline__ float f2sum(unsigned long long a) {
    return __uint_as_float((unsigned)a) + __uint_as_float((unsigned)(a >> 32));
}

// ---------------- kernel A: vm + visibility compaction ----------------
__global__ void vm_kernel(const float* __restrict__ logits) {
    const int b = blockIdx.x;
    __shared__ float sv[NV];
    __shared__ float smin[256];
    __shared__ float smax[256];
    __shared__ int c_inv, c_vis;
    float lmin = 1e30f, lmax = -1e30f;
    for (int i = threadIdx.x; i < NV; i += 256) {
        float s = 1.0f / (1.0f + expf(-logits[b * NV + i]));
        sv[i] = s;
        lmin = fminf(lmin, s);
        lmax = fmaxf(lmax, s);
    }
    smin[threadIdx.x] = lmin;
    smax[threadIdx.x] = lmax;
    if (threadIdx.x == 0) { c_inv = 0; c_vis = 0; }
    __syncthreads();
    for (int off = 128; off > 0; off >>= 1) {
        if (threadIdx.x < off) {
            smin[threadIdx.x] = fminf(smin[threadIdx.x], smin[threadIdx.x + off]);
            smax[threadIdx.x] = fmaxf(smax[threadIdx.x], smax[threadIdx.x + off]);
        }
        __syncthreads();
    }
    const float mn = smin[0];
    const float inv = 1.0f / (smax[0] - mn);
    for (int i = threadIdx.x; i < NV; i += 256) {
        float v = (sv[i] - mn) * inv;
        g_vm[b * NV + i] = v;
        if (v >= 0.5f) {
            int p = atomicAdd(&c_vis, 1);
            g_vis_list[b * NV + p] = i;
        } else {
            int p = atomicAdd(&c_inv, 1);
            g_invis_list[b * NV + p] = i;
        }
    }
    __syncthreads();
    if (threadIdx.x == 0) {
        g_vis_cnt[b] = c_vis;
        g_invis_cnt[b] = c_inv;
    }
}

// ---------------- kernel B: unit-normalize key features ----------------
__global__ void norm_kernel(const float* __restrict__ vf, const float* __restrict__ pf) {
    const int gw = (blockIdx.x * blockDim.x + threadIdx.x) >> 5;
    const int lane = threadIdx.x & 31;
    const int totalRows = BATCH * NV + BATCH * NP;
    if (gw >= totalRows) return;
    const float* src;
    float* dst;
    if (gw < BATCH * NV) {
        src = vf + (size_t)gw * DIM;
        dst = g_vf_unit + (size_t)gw * DIM;
    } else {
        const int r = gw - BATCH * NV;
        src = pf + (size_t)r * DIM;
        dst = g_pf_unit + (size_t)r * DIM;
    }
    float2 v = ((const float2*)src)[lane];
    float ss = v.x * v.x + v.y * v.y;
#pragma unroll
    for (int o = 16; o > 0; o >>= 1) ss += __shfl_xor_sync(0xffffffffu, ss, o);
    const float inv = 1.0f / fmaxf(sqrtf(ss), 1e-12f);
    float2 o2;
    o2.x = v.x * inv;
    o2.y = v.y * inv;
    ((float2*)dst)[lane] = o2;
}

// ---------------- stage 1: KNN vtx->pts + flow_init + output for all ----------------
// block = 256 thr = 8 warps; lane<->query (32 q/block); warp w scans keys [w*512, w*512+512)
__global__ __launch_bounds__(256, 2) void stage1_kernel(
    const float* __restrict__ vtx, const float* __restrict__ pts,
    const float* __restrict__ vf_raw, const float* __restrict__ pf_raw,
    float* __restrict__ out) {
    const int tid = threadIdx.x;
    const int w = tid >> 5;
    const int lane = tid & 31;
    const int qg = blockIdx.x * 32 + lane;
    const int b = qg >> 11;

    unsigned long long q2[32];
    {
        const ulonglong2* qr = (const ulonglong2*)(vf_raw + (size_t)qg * DIM);
#pragma unroll
        for (int i = 0; i < 16; i++) {
            ulonglong2 t2 = qr[i];
            q2[2 * i] = t2.x;
            q2[2 * i + 1] = t2.y;
        }
    }

    __shared__ ulonglong2 tile[8][16][16];  // 32 KB
    __shared__ float mval[64][32];          //  8 KB (candidate-major: conflict-free)
    __shared__ int midx[64][32];            //  8 KB

    float v[8];
    int id[8];
#pragma unroll
    for (int j = 0; j < 8; j++) { v[j] = -1e30f; id[j] = -1; }

    const ulonglong2* pfU = (const ulonglong2*)(g_pf_unit + (size_t)b * NP * DIM);
    const int chunkBase = w * 512;

    for (int t = 0; t < 32; t++) {
        const int keyBase = chunkBase + t * 16;
        const ulonglong2* src = pfU + (size_t)keyBase * 16;
        ulonglong2* dstT = &tile[w][0][0];
#pragma unroll
        for (int i = 0; i < 8; i++) dstT[lane + i * 32] = src[lane + i * 32];
        __syncwarp();
#pragma unroll
        for (int k = 0; k < 16; k++) {
            unsigned long long a0 = 0ull, a1 = 0ull, a2 = 0ull, a3 = 0ull;
#pragma unroll
            for (int d = 0; d < 16; d++) {
                ulonglong2 kv = tile[w][k][d];  // broadcast LDS.128, imm offset
                if (d & 1) {
                    fma2(a2, q2[2 * d], kv.x);
                    fma2(a3, q2[2 * d + 1], kv.y);
                } else {
                    fma2(a0, q2[2 * d], kv.x);
                    fma2(a1, q2[2 * d + 1], kv.y);
                }
            }
            float s = f2sum(add2(add2(a0, a2), add2(a1, a3)));
            if (s > v[0]) {
                v[0] = s;
                id[0] = keyBase + k;
#pragma unroll
                for (int j = 0; j < 7; j++) {
                    if (v[j] > v[j + 1]) {
                        float tv = v[j]; v[j] = v[j + 1]; v[j + 1] = tv;
                        int ti = id[j]; id[j] = id[j + 1]; id[j + 1] = ti;
                    }
                }
            }
        }
        __syncwarp();
    }

#pragma unroll
    for (int j = 0; j < 8; j++) {
        mval[w * 8 + j][lane] = v[j];
        midx[w * 8 + j][lane] = id[j];
    }
    __syncthreads();

    if (w == 0) {
        float bv[8];
        int bi[8];
#pragma unroll
        for (int j = 0; j < 8; j++) { bv[j] = -1e30f; bi[j] = -1; }
        for (int c = 0; c < 64; c++) {
            float s = mval[c][lane];
            if (s > bv[0]) {
                bv[0] = s;
                bi[0] = midx[c][lane];
#pragma unroll
                for (int j = 0; j < 7; j++) {
                    if (bv[j] > bv[j + 1]) {
                        float tv = bv[j]; bv[j] = bv[j + 1]; bv[j + 1] = tv;
                        int ti = bi[j]; bi[j] = bi[j + 1]; bi[j + 1] = ti;
                    }
                }
            }
        }
        const float vx = vtx[qg * 3 + 0];
        const float vy = vtx[qg * 3 + 1];
        const float vz = vtx[qg * 3 + 2];
        float n0 = 0.f, n1 = 0.f, n2 = 0.f, den = 0.f;
#pragma unroll
        for (int j = 0; j < 8; j++) {
            const int gp = b * NP + bi[j];
            const ulonglong2* pr = (const ulonglong2*)(pf_raw + (size_t)gp * DIM);
            unsigned long long a0 = 0ull, a1 = 0ull;
#pragma unroll
            for (int i = 0; i < 16; i++) {
                ulonglong2 pv = pr[i];
                fma2(a0, q2[2 * i], pv.x);
                fma2(a1, q2[2 * i + 1], pv.y);
            }
            const float f = f2sum(add2(a0, a1));
            n0 += (pts[gp * 3 + 0] - vx) * f;
            n1 += (pts[gp * 3 + 1] - vy) * f;
            n2 += (pts[gp * 3 + 2] - vz) * f;
            den += f;
        }
        const float invd = 1.0f / den;
        const float f0 = n0 * invd, f1 = n1 * invd, f2v = n2 * invd;
        g_flow[qg * 3 + 0] = f0;
        g_flow[qg * 3 + 1] = f1;
        g_flow[qg * 3 + 2] = f2v;
        out[qg * 4 + 0] = f0;
        out[qg * 4 + 1] = f1;
        out[qg * 4 + 2] = f2v;
        out[qg * 4 + 3] = g_vm[qg];
    }
}

// ---------------- stage 2: invisible queries x visible keys ----------------
// grid (64, BATCH): block handles 32 compacted invisible queries of batch blockIdx.y
__global__ __launch_bounds__(256, 2) void stage2_kernel(
    const float* __restrict__ vf_raw, float* __restrict__ out) {
    const int b = blockIdx.y;
    const int cnt = g_invis_cnt[b];
    const int base = blockIdx.x * 32;
    if (base >= cnt) return;
    const int tid = threadIdx.x;
    const int w = tid >> 5;
    const int lane = tid & 31;
    const int vcnt = g_vis_cnt[b];

    const int qslot = base + lane;
    const int qi = g_invis_list[b * NV + min(qslot, cnt - 1)];
    const int qg = b * NV + qi;

    unsigned long long q2[32];
    {
        const ulonglong2* qr = (const ulonglong2*)(vf_raw + (size_t)qg * DIM);
#pragma unroll
        for (int i = 0; i < 16; i++) {
            ulonglong2 t2 = qr[i];
            q2[2 * i] = t2.x;
            q2[2 * i + 1] = t2.y;
        }
    }

    __shared__ ulonglong2 tile[8][16][16];  // 32 KB
    __shared__ float mval[64][32];          //  8 KB
    __shared__ int midx[64][32];            //  8 KB
    // per-warp key-id staging overlaps this warp's own midx rows (midx written only after scan)
    int* skeyw = &midx[8 * w][0];

    float v[8];
    int id[8];
#pragma unroll
    for (int j = 0; j < 8; j++) { v[j] = -1e30f; id[j] = -1; }

    const float* vfU = g_vf_unit + (size_t)b * NV * DIM;
    const int* vlist = g_vis_list + b * NV;
    const int chunkBase = w * 256;

    if (chunkBase < vcnt) {
        for (int t = 0; t < 16; t++) {
            const int keyBase = chunkBase + t * 16;
            if (keyBase >= vcnt) break;
            if (lane < 16) skeyw[lane] = vlist[min(keyBase + lane, vcnt - 1)];
            __syncwarp();
            // gather 16 visible-key rows into the tile
#pragma unroll
            for (int i = 0; i < 8; i++) {
                const int e = lane + i * 32;
                const int kk = e >> 4;
                const int dd = e & 15;
                const int row = skeyw[kk];
                tile[w][kk][dd] = ((const ulonglong2*)(vfU + (size_t)row * DIM))[dd];
            }
            __syncwarp();
#pragma unroll
            for (int k = 0; k < 16; k++) {
                unsigned long long a0 = 0ull, a1 = 0ull, a2 = 0ull, a3 = 0ull;
#pragma unroll
                for (int d = 0; d < 16; d++) {
                    ulonglong2 kv = tile[w][k][d];
                    if (d & 1) {
                        fma2(a2, q2[2 * d], kv.x);
                        fma2(a3, q2[2 * d + 1], kv.y);
                    } else {
                        fma2(a0, q2[2 * d], kv.x);
                        fma2(a1, q2[2 * d + 1], kv.y);
                    }
                }
                float s = f2sum(add2(add2(a0, a2), add2(a1, a3)));
                s = (keyBase + k < vcnt) ? s : -1e30f;  // padding keys never selected
                if (s > v[0]) {
                    v[0] = s;
                    id[0] = skeyw[k];
#pragma unroll
                    for (int j = 0; j < 7; j++) {
                        if (v[j] > v[j + 1]) {
                            float tv = v[j]; v[j] = v[j + 1]; v[j + 1] = tv;
                            int ti = id[j]; id[j] = id[j + 1]; id[j + 1] = ti;
                        }
                    }
                }
            }
            __syncwarp();
        }
    }

#pragma unroll
    for (int j = 0; j < 8; j++) {
        mval[w * 8 + j][lane] = v[j];
        midx[w * 8 + j][lane] = id[j];
    }
    __syncthreads();

    if (w == 0) {
        float bv[8];
        int bi[8];
#pragma unroll
        for (int j = 0; j < 8; j++) { bv[j] = -1e30f; bi[j] = -1; }
        for (int c = 0; c < 64; c++) {
            float s = mval[c][lane];
            if (s > bv[0]) {
                bv[0] = s;
                bi[0] = midx[c][lane];
#pragma unroll
                for (int j = 0; j < 7; j++) {
                    if (bv[j] > bv[j + 1]) {
                        float tv = bv[j]; bv[j] = bv[j + 1]; bv[j + 1] = tv;
                        int ti = bi[j]; bi[j] = bi[j + 1]; bi[j + 1] = ti;
                    }
                }
            }
        }
        float n0 = 0.f, n1 = 0.f, n2 = 0.f, den = 0.f;
#pragma unroll
        for (int j = 0; j < 8; j++) {
            const int gv = b * NV + bi[j];
            const ulonglong2* kr = (const ulonglong2*)(vf_raw + (size_t)gv * DIM);
            unsigned long long a0 = 0ull, a1 = 0ull;
#pragma unroll
            for (int i = 0; i < 16; i++) {
                ulonglong2 kv = kr[i];
                fma2(a0, q2[2 * i], kv.x);
                fma2(a1, q2[2 * i + 1], kv.y);
            }
            const float f = f2sum(add2(a0, a1));
            n0 += g_flow[gv * 3 + 0] * f;
            n1 += g_flow[gv * 3 + 1] * f;
            n2 += g_flow[gv * 3 + 2] * f;
            den += f;
        }
        const float invd = 1.0f / den;
        if (qslot < cnt) {
            out[qg * 4 + 0] = n0 * invd;
            out[qg * 4 + 1] = n1 * invd;
            out[qg * 4 + 2] = n2 * invd;
            out[qg * 4 + 3] = g_vm[qg];
        }
    }
}

// ---------------- launch ----------------
extern "C" void kernel_launch(void* const* d_in, const int* in_sizes, int n_in,
                              void* d_out, int out_size) {
    const float* vtx = (const float*)d_in[0];
    const float* pts = (const float*)d_in[1];
    const float* vf = (const float*)d_in[2];
    const float* pf = (const float*)d_in[3];
    const float* vml = (const float*)d_in[4];
    float* out = (float*)d_out;

    vm_kernel<<<BATCH, 256>>>(vml);
    const int rows = BATCH * (NV + NP);
    norm_kernel<<<(rows * 32) / 256, 256>>>(vf, pf);
    stage1_kernel<<<(BATCH * NV) / 32, 256>>>(vtx, pts, vf, pf, out);
    stage2_kernel<<<dim3(64, BATCH), 256>>>(vf, out);
}

// round 4
// speedup vs baseline: 1.3797x; 1.1256x over previous
#include <cuda_runtime.h>
#include <math.h>

#define BATCH 8
#define NV 2048
#define NP 4096
#define DIM 64

// ---------------- scratch (device globals; no allocation) ----------------
__device__ float g_pf_unit[BATCH * NP * DIM];
__device__ float g_vf_unit[BATCH * NV * DIM];
__device__ float g_vm[BATCH * NV];
__device__ float g_flow[BATCH * NV * 3];
__device__ int   g_invis_list[BATCH * NV];
__device__ int   g_vis_list[BATCH * NV];
__device__ int   g_invis_cnt[BATCH];
__device__ int   g_vis_cnt[BATCH];

// ---------------- f32x2 helpers ----------------
__device__ __forceinline__ void fma2(unsigned long long& d, unsigned long long a,
                                     unsigned long long b) {
    asm("fma.rn.f32x2 %0, %1, %2, %0;" : "+l"(d) : "l"(a), "l"(b));
}
__device__ __forceinline__ unsigned long long add2(unsigned long long a, unsigned long long b) {
    unsigned long long d;
    asm("add.rn.f32x2 %0, %1, %2;" : "=l"(d) : "l"(a), "l"(b));
    return d;
}
__device__ __forceinline__ float f2sum(unsigned long long a) {
    return __uint_as_float((unsigned)a) + __uint_as_float((unsigned)(a >> 32));
}

// branchless sorted insert: v[0..7] ascending (v[0]=min). No branches inside.
__device__ __forceinline__ void topk_insert(float (&v)[8], int (&id)[8], float s, int sid,
                                            bool c) {
    v[0] = c ? s : v[0];
    id[0] = c ? sid : id[0];
#pragma unroll
    for (int j = 0; j < 7; j++) {
        const bool g = v[j] > v[j + 1];
        const float tv = g ? v[j + 1] : v[j];
        v[j + 1] = g ? v[j] : v[j + 1];
        v[j] = tv;
        const int ti = g ? id[j + 1] : id[j];
        id[j + 1] = g ? id[j] : id[j + 1];
        id[j] = ti;
    }
}

// ---------------- kernel A: vm + visibility compaction ----------------
__global__ void vm_kernel(const float* __restrict__ logits) {
    const int b = blockIdx.x;
    __shared__ float sv[NV];
    __shared__ float smin[256];
    __shared__ float smax[256];
    __shared__ int c_inv, c_vis;
    float lmin = 1e30f, lmax = -1e30f;
    for (int i = threadIdx.x; i < NV; i += 256) {
        float s = 1.0f / (1.0f + expf(-logits[b * NV + i]));
        sv[i] = s;
        lmin = fminf(lmin, s);
        lmax = fmaxf(lmax, s);
    }
    smin[threadIdx.x] = lmin;
    smax[threadIdx.x] = lmax;
    if (threadIdx.x == 0) { c_inv = 0; c_vis = 0; }
    __syncthreads();
    for (int off = 128; off > 0; off >>= 1) {
        if (threadIdx.x < off) {
            smin[threadIdx.x] = fminf(smin[threadIdx.x], smin[threadIdx.x + off]);
            smax[threadIdx.x] = fmaxf(smax[threadIdx.x], smax[threadIdx.x + off]);
        }
        __syncthreads();
    }
    const float mn = smin[0];
    const float inv = 1.0f / (smax[0] - mn);
    for (int i = threadIdx.x; i < NV; i += 256) {
        float v = (sv[i] - mn) * inv;
        g_vm[b * NV + i] = v;
        if (v >= 0.5f) {
            int p = atomicAdd(&c_vis, 1);
            g_vis_list[b * NV + p] = i;
        } else {
            int p = atomicAdd(&c_inv, 1);
            g_invis_list[b * NV + p] = i;
        }
    }
    __syncthreads();
    if (threadIdx.x == 0) {
        g_vis_cnt[b] = c_vis;
        g_invis_cnt[b] = c_inv;
    }
}

// ---------------- kernel B: unit-normalize key features ----------------
__global__ void norm_kernel(const float* __restrict__ vf, const float* __restrict__ pf) {
    const int gw = (blockIdx.x * blockDim.x + threadIdx.x) >> 5;
    const int lane = threadIdx.x & 31;
    const int totalRows = BATCH * NV + BATCH * NP;
    if (gw >= totalRows) return;
    const float* src;
    float* dst;
    if (gw < BATCH * NV) {
        src = vf + (size_t)gw * DIM;
        dst = g_vf_unit + (size_t)gw * DIM;
    } else {
        const int r = gw - BATCH * NV;
        src = pf + (size_t)r * DIM;
        dst = g_pf_unit + (size_t)r * DIM;
    }
    float2 v = ((const float2*)src)[lane];
    float ss = v.x * v.x + v.y * v.y;
#pragma unroll
    for (int o = 16; o > 0; o >>= 1) ss += __shfl_xor_sync(0xffffffffu, ss, o);
    const float inv = 1.0f / fmaxf(sqrtf(ss), 1e-12f);
    float2 o2;
    o2.x = v.x * inv;
    o2.y = v.y * inv;
    ((float2*)dst)[lane] = o2;
}

// ---------------- stage 1: KNN vtx->pts + flow_init + output for all ----------------
// block = 128 thr = 4 warps; lane<->query (32 q/block); warp w scans keys [w*1024,+1024)
__global__ __launch_bounds__(128, 4) void stage1_kernel(
    const float* __restrict__ vtx, const float* __restrict__ pts,
    const float* __restrict__ vf_raw, const float* __restrict__ pf_raw,
    float* __restrict__ out) {
    const int tid = threadIdx.x;
    const int w = tid >> 5;
    const int lane = tid & 31;
    const int qg = blockIdx.x * 32 + lane;
    const int b = qg >> 11;

    unsigned long long q2[32];
    {
        const ulonglong2* qr = (const ulonglong2*)(vf_raw + (size_t)qg * DIM);
#pragma unroll
        for (int i = 0; i < 16; i++) {
            ulonglong2 t2 = qr[i];
            q2[2 * i] = t2.x;
            q2[2 * i + 1] = t2.y;
        }
    }

    __shared__ ulonglong2 tile[4][16][16];  // 16 KB
    __shared__ float mval[32][32];          //  4 KB (candidate-major)
    __shared__ int midx[32][32];            //  4 KB

    float v[8];
    int id[8];
#pragma unroll
    for (int j = 0; j < 8; j++) { v[j] = -1e30f; id[j] = -1; }

    const ulonglong2* pfU = (const ulonglong2*)(g_pf_unit + (size_t)b * NP * DIM);
    const int chunkBase = w * 1024;

    for (int t = 0; t < 64; t++) {
        const int keyBase = chunkBase + t * 16;
        const ulonglong2* src = pfU + (size_t)keyBase * 16;
        ulonglong2* dstT = &tile[w][0][0];
#pragma unroll
        for (int i = 0; i < 8; i++) dstT[lane + i * 32] = src[lane + i * 32];
        __syncwarp();
#pragma unroll
        for (int k = 0; k < 16; k++) {
            unsigned long long a0 = 0ull, a1 = 0ull, a2 = 0ull, a3 = 0ull;
#pragma unroll
            for (int d = 0; d < 16; d++) {
                ulonglong2 kv = tile[w][k][d];
                if (d & 1) {
                    fma2(a2, q2[2 * d], kv.x);
                    fma2(a3, q2[2 * d + 1], kv.y);
                } else {
                    fma2(a0, q2[2 * d], kv.x);
                    fma2(a1, q2[2 * d + 1], kv.y);
                }
            }
            const float s = f2sum(add2(add2(a0, a2), add2(a1, a3)));
            const bool c = s > v[0];
            if (__ballot_sync(0xffffffffu, c)) topk_insert(v, id, s, keyBase + k, c);
        }
        __syncwarp();
    }

#pragma unroll
    for (int j = 0; j < 8; j++) {
        mval[w * 8 + j][lane] = v[j];
        midx[w * 8 + j][lane] = id[j];
    }
    __syncthreads();

    if (w == 0) {
        float bv[8];
        int bi[8];
#pragma unroll
        for (int j = 0; j < 8; j++) { bv[j] = -1e30f; bi[j] = -1; }
        for (int c = 0; c < 32; c++) {
            const float s = mval[c][lane];
            const bool cc = s > bv[0];
            if (__ballot_sync(0xffffffffu, cc)) topk_insert(bv, bi, s, midx[c][lane], cc);
        }
        const float vx = vtx[qg * 3 + 0];
        const float vy = vtx[qg * 3 + 1];
        const float vz = vtx[qg * 3 + 2];
        float n0 = 0.f, n1 = 0.f, n2 = 0.f, den = 0.f;
#pragma unroll
        for (int j = 0; j < 8; j++) {
            const int gp = b * NP + bi[j];
            const ulonglong2* pr = (const ulonglong2*)(pf_raw + (size_t)gp * DIM);
            unsigned long long a0 = 0ull, a1 = 0ull;
#pragma unroll
            for (int i = 0; i < 16; i++) {
                ulonglong2 pv = pr[i];
                fma2(a0, q2[2 * i], pv.x);
                fma2(a1, q2[2 * i + 1], pv.y);
            }
            const float f = f2sum(add2(a0, a1));
            n0 += (pts[gp * 3 + 0] - vx) * f;
            n1 += (pts[gp * 3 + 1] - vy) * f;
            n2 += (pts[gp * 3 + 2] - vz) * f;
            den += f;
        }
        const float invd = 1.0f / den;
        const float f0 = n0 * invd, f1 = n1 * invd, f2v = n2 * invd;
        g_flow[qg * 3 + 0] = f0;
        g_flow[qg * 3 + 1] = f1;
        g_flow[qg * 3 + 2] = f2v;
        out[qg * 4 + 0] = f0;
        out[qg * 4 + 1] = f1;
        out[qg * 4 + 2] = f2v;
        out[qg * 4 + 3] = g_vm[qg];
    }
}

// ---------------- stage 2: invisible queries x visible keys ----------------
// grid (64, BATCH): block = 32 compacted invisible queries; 4 warps split the visible keys
__global__ __launch_bounds__(128, 4) void stage2_kernel(
    const float* __restrict__ vf_raw, float* __restrict__ out) {
    const int b = blockIdx.y;
    const int cnt = g_invis_cnt[b];
    const int base = blockIdx.x * 32;
    if (base >= cnt) return;
    const int tid = threadIdx.x;
    const int w = tid >> 5;
    const int lane = tid & 31;
    const int vcnt = g_vis_cnt[b];

    const int qslot = base + lane;
    const int qi = g_invis_list[b * NV + min(qslot, cnt - 1)];
    const int qg = b * NV + qi;

    unsigned long long q2[32];
    {
        const ulonglong2* qr = (const ulonglong2*)(vf_raw + (size_t)qg * DIM);
#pragma unroll
        for (int i = 0; i < 16; i++) {
            ulonglong2 t2 = qr[i];
            q2[2 * i] = t2.x;
            q2[2 * i + 1] = t2.y;
        }
    }

    __shared__ ulonglong2 tile[4][16][16];  // 16 KB
    __shared__ float mval[32][32];          //  4 KB
    __shared__ int midx[32][32];            //  4 KB
    int* skeyw = &midx[8 * w][0];  // staging: overwritten only after scan completes

    float v[8];
    int id[8];
#pragma unroll
    for (int j = 0; j < 8; j++) { v[j] = -1e30f; id[j] = -1; }

    const float* vfU = g_vf_unit + (size_t)b * NV * DIM;
    const int* vlist = g_vis_list + b * NV;

    // split tiles of 16 keys evenly across the 4 warps
    const int ntiles = (vcnt + 15) >> 4;
    const int tpw = (ntiles + 3) >> 2;
    const int t0 = w * tpw;
    const int t1 = min(ntiles, t0 + tpw);

    for (int t = t0; t < t1; t++) {
        const int keyBase = t * 16;
        if (lane < 16) skeyw[lane] = vlist[min(keyBase + lane, vcnt - 1)];
        __syncwarp();
#pragma unroll
        for (int i = 0; i < 8; i++) {
            const int e = lane + i * 32;
            const int kk = e >> 4;
            const int dd = e & 15;
            const int row = skeyw[kk];
            tile[w][kk][dd] = ((const ulonglong2*)(vfU + (size_t)row * DIM))[dd];
        }
        __syncwarp();
#pragma unroll
        for (int k = 0; k < 16; k++) {
            unsigned long long a0 = 0ull, a1 = 0ull, a2 = 0ull, a3 = 0ull;
#pragma unroll
            for (int d = 0; d < 16; d++) {
                ulonglong2 kv = tile[w][k][d];
                if (d & 1) {
                    fma2(a2, q2[2 * d], kv.x);
                    fma2(a3, q2[2 * d + 1], kv.y);
                } else {
                    fma2(a0, q2[2 * d], kv.x);
                    fma2(a1, q2[2 * d + 1], kv.y);
                }
            }
            float s = f2sum(add2(add2(a0, a2), add2(a1, a3)));
            s = (keyBase + k < vcnt) ? s : -1e30f;
            const bool c = s > v[0];
            if (__ballot_sync(0xffffffffu, c)) topk_insert(v, id, s, skeyw[k], c);
        }
        __syncwarp();
    }

#pragma unroll
    for (int j = 0; j < 8; j++) {
        mval[w * 8 + j][lane] = v[j];
        midx[w * 8 + j][lane] = id[j];
    }
    __syncthreads();

    if (w == 0) {
        float bv[8];
        int bi[8];
#pragma unroll
        for (int j = 0; j < 8; j++) { bv[j] = -1e30f; bi[j] = -1; }
        for (int c = 0; c < 32; c++) {
            const float s = mval[c][lane];
            const bool cc = s > bv[0];
            if (__ballot_sync(0xffffffffu, cc)) topk_insert(bv, bi, s, midx[c][lane], cc);
        }
        float n0 = 0.f, n1 = 0.f, n2 = 0.f, den = 0.f;
#pragma unroll
        for (int j = 0; j < 8; j++) {
            const int gv = b * NV + bi[j];
            const ulonglong2* kr = (const ulonglong2*)(vf_raw + (size_t)gv * DIM);
            unsigned long long a0 = 0ull, a1 = 0ull;
#pragma unroll
            for (int i = 0; i < 16; i++) {
                ulonglong2 kv = kr[i];
                fma2(a0, q2[2 * i], kv.x);
                fma2(a1, q2[2 * i + 1], kv.y);
            }
            const float f = f2sum(add2(a0, a1));
            n0 += g_flow[gv * 3 + 0] * f;
            n1 += g_flow[gv * 3 + 1] * f;
            n2 += g_flow[gv * 3 + 2] * f;
            den += f;
        }
        const float invd = 1.0f / den;
        if (qslot < cnt) {
            out[qg * 4 + 0] = n0 * invd;
            out[qg * 4 + 1] = n1 * invd;
            out[qg * 4 + 2] = n2 * invd;
            out[qg * 4 + 3] = g_vm[qg];
        }
    }
}

// ---------------- launch ----------------
extern "C" void kernel_launch(void* const* d_in, const int* in_sizes, int n_in,
                              void* d_out, int out_size) {
    const float* vtx = (const float*)d_in[0];
    const float* pts = (const float*)d_in[1];
    const float* vf = (const float*)d_in[2];
    const float* pf = (const float*)d_in[3];
    const float* vml = (const float*)d_in[4];
    float* out = (float*)d_out;

    vm_kernel<<<BATCH, 256>>>(vml);
    const int rows = BATCH * (NV + NP);
    norm_kernel<<<(rows * 32) / 256, 256>>>(vf, pf);
    stage1_kernel<<<(BATCH * NV) / 32, 128>>>(vtx, pts, vf, pf, out);
    stage2_kernel<<<dim3(64, BATCH), 128>>>(vf, out);
}

// round 5
// speedup vs baseline: 1.6348x; 1.1849x over previous
#include <cuda_runtime.h>
#include <math.h>

#define BATCH 8
#define NV 2048
#define NP 4096
#define DIM 64
#define S1_BLOCKS 512   // (BATCH*NV)/32
#define S2_BLOCKS 512   // 64 per batch (worst case all-invisible)

// ---------------- scratch (device globals; no allocation) ----------------
__device__ float g_pf_unit[BATCH * NP * DIM];
__device__ float g_vf_unit[BATCH * NV * DIM];
__device__ float g_vm[BATCH * NV];
__device__ float g_flow[BATCH * NV * 3];
__device__ int   g_invis_list[BATCH * NV];
__device__ int   g_vis_list[BATCH * NV];
__device__ int   g_invis_cnt[BATCH];
__device__ int   g_vis_cnt[BATCH];
__device__ int   g_s2idx[BATCH * NV * 8];   // stage2 top-8 neighbor ids per invis query

// ---------------- f32x2 helpers ----------------
__device__ __forceinline__ void fma2(unsigned long long& d, unsigned long long a,
                                     unsigned long long b) {
    asm("fma.rn.f32x2 %0, %1, %2, %0;" : "+l"(d) : "l"(a), "l"(b));
}
__device__ __forceinline__ unsigned long long add2(unsigned long long a, unsigned long long b) {
    unsigned long long d;
    asm("add.rn.f32x2 %0, %1, %2;" : "=l"(d) : "l"(a), "l"(b));
    return d;
}
__device__ __forceinline__ float f2sum(unsigned long long a) {
    return __uint_as_float((unsigned)a) + __uint_as_float((unsigned)(a >> 32));
}

// branchless sorted insert, v[0..7] ascending; FMNMX + pred-as-data selects
__device__ __forceinline__ void topk_insert(float (&v)[8], int (&id)[8], float s, int sid,
                                            bool c) {
    v[0] = c ? s : v[0];
    id[0] = c ? sid : id[0];
#pragma unroll
    for (int j = 0; j < 7; j++) {
        const bool g = v[j] > v[j + 1];
        const float lo = fminf(v[j], v[j + 1]);
        const float hi = fmaxf(v[j], v[j + 1]);
        const int tlo = g ? id[j + 1] : id[j];
        const int thi = g ? id[j] : id[j + 1];
        v[j] = lo;
        v[j + 1] = hi;
        id[j] = tlo;
        id[j + 1] = thi;
    }
}

// ---------------- kernel A: vm + visibility compaction ----------------
__global__ void vm_kernel(const float* __restrict__ logits) {
    const int b = blockIdx.x;
    __shared__ float sv[NV];
    __shared__ float smin[256];
    __shared__ float smax[256];
    __shared__ int c_inv, c_vis;
    float lmin = 1e30f, lmax = -1e30f;
    for (int i = threadIdx.x; i < NV; i += 256) {
        float s = 1.0f / (1.0f + expf(-logits[b * NV + i]));
        sv[i] = s;
        lmin = fminf(lmin, s);
        lmax = fmaxf(lmax, s);
    }
    smin[threadIdx.x] = lmin;
    smax[threadIdx.x] = lmax;
    if (threadIdx.x == 0) { c_inv = 0; c_vis = 0; }
    __syncthreads();
    for (int off = 128; off > 0; off >>= 1) {
        if (threadIdx.x < off) {
            smin[threadIdx.x] = fminf(smin[threadIdx.x], smin[threadIdx.x + off]);
            smax[threadIdx.x] = fmaxf(smax[threadIdx.x], smax[threadIdx.x + off]);
        }
        __syncthreads();
    }
    const float mn = smin[0];
    const float inv = 1.0f / (smax[0] - mn);
    for (int i = threadIdx.x; i < NV; i += 256) {
        float v = (sv[i] - mn) * inv;
        g_vm[b * NV + i] = v;
        if (v >= 0.5f) {
            int p = atomicAdd(&c_vis, 1);
            g_vis_list[b * NV + p] = i;
        } else {
            int p = atomicAdd(&c_inv, 1);
            g_invis_list[b * NV + p] = i;
        }
    }
    __syncthreads();
    if (threadIdx.x == 0) {
        g_vis_cnt[b] = c_vis;
        g_invis_cnt[b] = c_inv;
    }
}

// ---------------- kernel B: unit-normalize key features ----------------
__global__ void norm_kernel(const float* __restrict__ vf, const float* __restrict__ pf) {
    const int gw = (blockIdx.x * blockDim.x + threadIdx.x) >> 5;
    const int lane = threadIdx.x & 31;
    const int totalRows = BATCH * NV + BATCH * NP;
    if (gw >= totalRows) return;
    const float* src;
    float* dst;
    if (gw < BATCH * NV) {
        src = vf + (size_t)gw * DIM;
        dst = g_vf_unit + (size_t)gw * DIM;
    } else {
        const int r = gw - BATCH * NV;
        src = pf + (size_t)r * DIM;
        dst = g_pf_unit + (size_t)r * DIM;
    }
    float2 v = ((const float2*)src)[lane];
    float ss = v.x * v.x + v.y * v.y;
#pragma unroll
    for (int o = 16; o > 0; o >>= 1) ss += __shfl_xor_sync(0xffffffffu, ss, o);
    const float inv = 1.0f / fmaxf(sqrtf(ss), 1e-12f);
    float2 o2;
    o2.x = v.x * inv;
    o2.y = v.y * inv;
    ((float2*)dst)[lane] = o2;
}

// 2-key dot over a 16-key tile with top-8 maintenance
__device__ __forceinline__ void scan_tile(const ulonglong2 (*tileW)[16],
                                          const unsigned long long (&q2)[32],
                                          float (&v)[8], int (&id)[8],
                                          int idBase, const int* sid /*or nullptr*/,
                                          int validLimit /*keys >= limit masked*/) {
#pragma unroll
    for (int k = 0; k < 16; k += 2) {
        unsigned long long a0 = 0ull, a1 = 0ull, b0 = 0ull, b1 = 0ull;
#pragma unroll
        for (int d = 0; d < 16; d++) {
            const ulonglong2 kva = tileW[k][d];
            const ulonglong2 kvb = tileW[k + 1][d];
            fma2(a0, q2[2 * d], kva.x);
            fma2(a1, q2[2 * d + 1], kva.y);
            fma2(b0, q2[2 * d], kvb.x);
            fma2(b1, q2[2 * d + 1], kvb.y);
        }
        float sA = f2sum(add2(a0, a1));
        float sB = f2sum(add2(b0, b1));
        sA = (k < validLimit) ? sA : -1e30f;
        sB = (k + 1 < validLimit) ? sB : -1e30f;
        const int idA = sid ? sid[k] : (idBase + k);
        const int idB = sid ? sid[k + 1] : (idBase + k + 1);
        const bool cA = sA > v[0];
        if (__ballot_sync(0xffffffffu, cA)) topk_insert(v, id, sA, idA, cA);
        const bool cB = sB > v[0];
        if (__ballot_sync(0xffffffffu, cB)) topk_insert(v, id, sB, idB, cB);
    }
}

// ---------------- fused kernel: stage1 (full) + stage2 KNN scan ----------------
// blocks [0,512): stage1 for queries bid*32..+32 (4 warps x 1024-key chunks)
// blocks [512,1024): stage2 scan for invis queries; writes top-8 ids to g_s2idx
__global__ __launch_bounds__(128, 4) void fused_kernel(
    const float* __restrict__ vtx, const float* __restrict__ pts,
    const float* __restrict__ vf_raw, const float* __restrict__ pf_raw,
    float* __restrict__ out) {
    const int tid = threadIdx.x;
    const int w = tid >> 5;
    const int lane = tid & 31;

    __shared__ ulonglong2 tile[4][16][16];  // 16 KB
    __shared__ float mval[32][32];          //  4 KB (candidate-major)
    __shared__ int midx[32][32];            //  4 KB

    float v[8];
    int id[8];
#pragma unroll
    for (int j = 0; j < 8; j++) { v[j] = -1e30f; id[j] = -1; }

    if (blockIdx.x < S1_BLOCKS) {
        // ================= stage 1 =================
        const int qg = blockIdx.x * 32 + lane;
        const int b = qg >> 11;

        unsigned long long q2[32];
        {
            const ulonglong2* qr = (const ulonglong2*)(vf_raw + (size_t)qg * DIM);
#pragma unroll
            for (int i = 0; i < 16; i++) {
                ulonglong2 t2 = qr[i];
                q2[2 * i] = t2.x;
                q2[2 * i + 1] = t2.y;
            }
        }

        const ulonglong2* pfU = (const ulonglong2*)(g_pf_unit + (size_t)b * NP * DIM);
        const int chunkBase = w * 1024;

        for (int t = 0; t < 64; t++) {
            const int keyBase = chunkBase + t * 16;
            const ulonglong2* src = pfU + (size_t)keyBase * 16;
            ulonglong2* dstT = &tile[w][0][0];
#pragma unroll
            for (int i = 0; i < 8; i++) dstT[lane + i * 32] = src[lane + i * 32];
            __syncwarp();
            scan_tile(tile[w], q2, v, id, keyBase, nullptr, 16);
            __syncwarp();
        }

#pragma unroll
        for (int j = 0; j < 8; j++) {
            mval[w * 8 + j][lane] = v[j];
            midx[w * 8 + j][lane] = id[j];
        }
        __syncthreads();

        if (w == 0) {
            float bv[8];
            int bi[8];
#pragma unroll
            for (int j = 0; j < 8; j++) { bv[j] = -1e30f; bi[j] = -1; }
            for (int c = 0; c < 32; c++) {
                const float s = mval[c][lane];
                const bool cc = s > bv[0];
                if (__ballot_sync(0xffffffffu, cc)) topk_insert(bv, bi, s, midx[c][lane], cc);
            }
            const float vx = vtx[qg * 3 + 0];
            const float vy = vtx[qg * 3 + 1];
            const float vz = vtx[qg * 3 + 2];
            float n0 = 0.f, n1 = 0.f, n2 = 0.f, den = 0.f;
#pragma unroll
            for (int j = 0; j < 8; j++) {
                const int gp = b * NP + bi[j];
                const ulonglong2* pr = (const ulonglong2*)(pf_raw + (size_t)gp * DIM);
                unsigned long long a0 = 0ull, a1 = 0ull;
#pragma unroll
                for (int i = 0; i < 16; i++) {
                    ulonglong2 pv = pr[i];
                    fma2(a0, q2[2 * i], pv.x);
                    fma2(a1, q2[2 * i + 1], pv.y);
                }
                const float f = f2sum(add2(a0, a1));
                n0 += (pts[gp * 3 + 0] - vx) * f;
                n1 += (pts[gp * 3 + 1] - vy) * f;
                n2 += (pts[gp * 3 + 2] - vz) * f;
                den += f;
            }
            const float invd = 1.0f / den;
            const float f0 = n0 * invd, f1 = n1 * invd, f2v = n2 * invd;
            g_flow[qg * 3 + 0] = f0;
            g_flow[qg * 3 + 1] = f1;
            g_flow[qg * 3 + 2] = f2v;
            out[qg * 4 + 0] = f0;
            out[qg * 4 + 1] = f1;
            out[qg * 4 + 2] = f2v;
            out[qg * 4 + 3] = g_vm[qg];
        }
    } else {
        // ================= stage 2 scan =================
        const int sb = blockIdx.x - S1_BLOCKS;  // [0,512)
        const int b = sb >> 6;                  // 64 blocks per batch
        const int cnt = g_invis_cnt[b];
        const int base = (sb & 63) * 32;
        if (base >= cnt) return;
        const int vcnt = g_vis_cnt[b];

        const int qslot = base + lane;
        const int qi = g_invis_list[b * NV + min(qslot, cnt - 1)];
        const int qg = b * NV + qi;

        unsigned long long q2[32];
        {
            const ulonglong2* qr = (const ulonglong2*)(vf_raw + (size_t)qg * DIM);
#pragma unroll
            for (int i = 0; i < 16; i++) {
                ulonglong2 t2 = qr[i];
                q2[2 * i] = t2.x;
                q2[2 * i + 1] = t2.y;
            }
        }
        int* skeyw = &midx[8 * w][0];  // staging; midx rewritten only after scan

        const float* vfU = g_vf_unit + (size_t)b * NV * DIM;
        const int* vlist = g_vis_list + b * NV;

        const int ntiles = (vcnt + 15) >> 4;
        const int tpw = (ntiles + 3) >> 2;
        const int t0 = w * tpw;
        const int t1 = min(ntiles, t0 + tpw);

        for (int t = t0; t < t1; t++) {
            const int keyBase = t * 16;
            if (lane < 16) skeyw[lane] = vlist[min(keyBase + lane, vcnt - 1)];
            __syncwarp();
#pragma unroll
            for (int i = 0; i < 8; i++) {
                const int e = lane + i * 32;
                const int kk = e >> 4;
                const int dd = e & 15;
                const int row = skeyw[kk];
                tile[w][kk][dd] = ((const ulonglong2*)(vfU + (size_t)row * DIM))[dd];
            }
            __syncwarp();
            scan_tile(tile[w], q2, v, id, 0, skeyw, vcnt - keyBase);
            __syncwarp();
        }

#pragma unroll
        for (int j = 0; j < 8; j++) {
            mval[w * 8 + j][lane] = v[j];
            midx[w * 8 + j][lane] = id[j];
        }
        __syncthreads();

        if (w == 0) {
            float bv[8];
            int bi[8];
#pragma unroll
            for (int j = 0; j < 8; j++) { bv[j] = -1e30f; bi[j] = -1; }
            for (int c = 0; c < 32; c++) {
                const float s = mval[c][lane];
                const bool cc = s > bv[0];
                if (__ballot_sync(0xffffffffu, cc)) topk_insert(bv, bi, s, midx[c][lane], cc);
            }
            if (qslot < cnt) {
#pragma unroll
                for (int j = 0; j < 8; j++) g_s2idx[qg * 8 + j] = bi[j];
            }
        }
    }
}

// ---------------- epilogue: invisible flow from stage2 neighbors ----------------
// grid (256, BATCH), 256 thr = 8 warps; warp <-> one invisible query
__global__ __launch_bounds__(256) void epilogue_kernel(
    const float* __restrict__ vf_raw, float* __restrict__ out) {
    const int b = blockIdx.y;
    const int cnt = g_invis_cnt[b];
    const int w = threadIdx.x >> 5;
    const int lane = threadIdx.x & 31;
    const int qslot = blockIdx.x * 8 + w;
    if (qslot >= cnt) return;
    const int qi = g_invis_list[b * NV + qslot];
    const int qg = b * NV + qi;

    float n0 = 0.f, n1 = 0.f, n2 = 0.f, den = 0.f;
    if (lane < 8) {
        const int gv = b * NV + g_s2idx[qg * 8 + lane];
        const float4* qr = (const float4*)(vf_raw + (size_t)qg * DIM);
        const float4* kr = (const float4*)(vf_raw + (size_t)gv * DIM);
        float f0 = 0.f, f1 = 0.f, f2 = 0.f, f3 = 0.f;
#pragma unroll
        for (int i = 0; i < 16; i++) {
            const float4 qv = qr[i];
            const float4 kv = kr[i];
            f0 += qv.x * kv.x;
            f1 += qv.y * kv.y;
            f2 += qv.z * kv.z;
            f3 += qv.w * kv.w;
        }
        const float f = (f0 + f1) + (f2 + f3);
        n0 = g_flow[gv * 3 + 0] * f;
        n1 = g_flow[gv * 3 + 1] * f;
        n2 = g_flow[gv * 3 + 2] * f;
        den = f;
    }
#pragma unroll
    for (int o = 4; o > 0; o >>= 1) {
        n0 += __shfl_down_sync(0xffffffffu, n0, o);
        n1 += __shfl_down_sync(0xffffffffu, n1, o);
        n2 += __shfl_down_sync(0xffffffffu, n2, o);
        den += __shfl_down_sync(0xffffffffu, den, o);
    }
    if (lane == 0) {
        const float invd = 1.0f / den;
        out[qg * 4 + 0] = n0 * invd;
        out[qg * 4 + 1] = n1 * invd;
        out[qg * 4 + 2] = n2 * invd;
        out[qg * 4 + 3] = g_vm[qg];
    }
}

// ---------------- launch ----------------
extern "C" void kernel_launch(void* const* d_in, const int* in_sizes, int n_in,
                              void* d_out, int out_size) {
    const float* vtx = (const float*)d_in[0];
    const float* pts = (const float*)d_in[1];
    const float* vf = (const float*)d_in[2];
    const float* pf = (const float*)d_in[3];
    const float* vml = (const float*)d_in[4];
    float* out = (float*)d_out;

    vm_kernel<<<BATCH, 256>>>(vml);
    const int rows = BATCH * (NV + NP);
    norm_kernel<<<(rows * 32) / 256, 256>>>(vf, pf);
    fused_kernel<<<S1_BLOCKS + S2_BLOCKS, 128>>>(vtx, pts, vf, pf, out);
    epilogue_kernel<<<dim3(256, BATCH), 256>>>(vf, out);
}